// round 13
// baseline (speedup 1.0000x reference)
#include <cuda_runtime.h>
#include <cuda_fp16.h>
#include <cstdint>
#include <math.h>

// fp16 m16n8k16 mma conv (fp32 accum), cp.async double-buffered pipeline.
// R13: 8-warp CTA over 2 images; per-warp tile mp=4 x n=8 (128B/MMA);
// weights staged once per image pair.
#define PIX   256
#define BATCH 128
#define STEPS 6

// scratch offsets (floats)
#define OFF_STATIC_Q 0u
#define OFF_STATIC_P 16777216u
#define OFF_GATES    33554432u
#define OFF_CP       50331648u
#define OFF_CQ       54525952u
#define OFF_RQ       58720256u
#define OFF_RP       62914560u
#define OFF_Z        67108864u
#define OFF_KLB      69206016u
#define OFF_LPQB     69206144u
#define OFF_PW_SSM   69206272u
#define OFF_PW_Q     71356672u
#define OFF_PW_P     74735872u
#define OFF_PW_RQ    77705472u
#define OFF_PW_RP    77910272u
// fp16 padded planes: per (b,chunk16) = 640 pix * 12 u32 = 7680 u32 (30720 B)
#define OFF_PAD_C    78115072u
#define OFF_PAD_D    85979392u
#define OFF_PAD_A    93843712u
#define OFF_PAD_STMO 94826752u
#define OFF_PAD_ZTMO 102691072u
#define OFF_PAD_ST   106623232u
#define OFF_PAD_HP   114487552u
#define OFF_PAD_HQ   122351872u
#define OFF_PAD_ZB   130216192u
#define SCRATCH_N    134148352u
// pad_st + pad_hp + pad_hq + pad_zb (floats)
#define PAD_STATE_FLOATS 27525120u

__device__ float g_scratch[SCRATCH_N];

__device__ __forceinline__ void mma_f16(float& c0, float& c1, float& c2, float& c3,
                                        uint32_t a0, uint32_t a1, uint32_t a2, uint32_t a3,
                                        uint32_t b0, uint32_t b1) {
    asm volatile(
        "mma.sync.aligned.m16n8k16.row.col.f32.f16.f16.f32 "
        "{%0,%1,%2,%3}, {%4,%5,%6,%7}, {%8,%9}, {%0,%1,%2,%3};"
        : "+f"(c0), "+f"(c1), "+f"(c2), "+f"(c3)
        : "r"(a0), "r"(a1), "r"(a2), "r"(a3), "r"(b0), "r"(b1));
}
__device__ __forceinline__ void cpasync16(uint32_t s, const void* g) {
    asm volatile("cp.async.cg.shared.global [%0], [%1], 16;" :: "r"(s), "l"(g));
}
__device__ __forceinline__ void cpcommit() { asm volatile("cp.async.commit_group;"); }
__device__ __forceinline__ uint32_t pack_h2(float lo, float hi) {
    __half2 h = __floats2half2_rn(lo, hi);
    return *reinterpret_cast<uint32_t*>(&h);
}

// ---------------- weight repack (fp16 fragments) ----------------
// PW per (cg64, chunk16): [tap25][mp4][lane32][slot4] uint32 = 12800 u32.
struct RepackJobs {
    const float* W[5]; float* PW[5];
    int cinSrc[5], nch[5], nSeg[5];
    int segPad[5][5], segLen[5][5], segSrc[5][5];
    int start[6];
};
__device__ __forceinline__ float w_lookup(const RepackJobs& J, int j, int co, int ci, int tap) {
    int s = J.nSeg[j] - 1;
    for (int t = 1; t < J.nSeg[j]; ++t) if (ci < J.segPad[j][t]) { s = t - 1; break; }
    int off = ci - J.segPad[j][s];
    if (off >= J.segLen[j][s]) return 0.f;
    return J.W[j][((size_t)co * J.cinSrc[j] + J.segSrc[j][s] + off) * 25 + tap];
}
__global__ void repack_all_kernel(RepackJobs J) {
    int idx = blockIdx.x * 256 + threadIdx.x;
    if (idx >= J.start[5]) return;
    int j = 0; while (idx >= J.start[j + 1]) ++j;
    int L = idx - J.start[j];
    int s = L & 3, lane = (L >> 2) & 31, mp = (L >> 7) & 3;
    int rest = L >> 9;
    int tap = rest % 25, rest2 = rest / 25;
    int chunk = rest2 % J.nch[j], cg = rest2 / J.nch[j];
    int g = lane >> 2, tig = lane & 3;
    int co  = cg * 64 + mp * 16 + (s & 1) * 8 + g;
    int ci0 = chunk * 16 + 2 * tig + (s >> 1) * 8;
    reinterpret_cast<uint32_t*>(J.PW[j])[L] =
        pack_h2(w_lookup(J, j, co, ci0, tap), w_lookup(J, j, co, ci0 + 1, tap));
}

// ---------------- padify (fp16 planes) ----------------
struct PadJobs {
    const float* src[5]; __half* dst[5];
    int cinReal[5], nch[5];
    int start[6];
};
__global__ void padify_all_kernel(PadJobs J) {
    int idx = blockIdx.x * 256 + threadIdx.x;
    if (idx >= J.start[5]) return;
    int j = 0; while (idx >= J.start[j + 1]) ++j;
    int L = idx - J.start[j];
    int u = L & 7;
    int pix = (L >> 3) % 640;
    int rest = L / (640 * 8);
    int ch = rest % J.nch[j], b = rest / J.nch[j];
    int row = pix >> 5, col = pix & 31;
    float v0 = 0.f, v1 = 0.f;
    if ((unsigned)(row - 2) < 16u && (unsigned)(col - 2) < 16u) {
        int ci0 = ch * 16 + 2 * u;
        int p = (row - 2) * 16 + (col - 2);
        if (ci0 < J.cinReal[j])     v0 = J.src[j][((size_t)b * J.cinReal[j] + ci0) * 256 + p];
        if (ci0 + 1 < J.cinReal[j]) v1 = J.src[j][((size_t)b * J.cinReal[j] + ci0 + 1) * 256 + p];
    }
    reinterpret_cast<uint32_t*>(J.dst[j])[((size_t)(b * J.nch[j] + ch) * 640 + pix) * 12 + u] =
        pack_h2(v0, v1);
}

// ---------------- conv ----------------
struct Seg { const __half* pad; int nch; int startChunk; };
struct ConvArgs {
    Seg seg[4]; int nseg;
    const float* PW; int nChunks;
    const float* bias; const float* base;
    float* out; int cout;
};
#define A_BYTES     51200
#define PLANE_BYTES 30720
#define BUF_BYTES   (A_BYTES + 2 * PLANE_BYTES)   // 112640
#define CONV_SMEM_BYTES (2 * BUF_BYTES)           // 225280
#define CONV_THREADS 256

// CTA: 64 couts x 2 images x 256 pixels. Warps 0-3 -> image 2*by, 4-7 -> 2*by+1.
__global__ void __launch_bounds__(CONV_THREADS, 1) conv5x5_mma_kernel(ConvArgs a) {
    extern __shared__ char smem[];
    const int by = blockIdx.y, cg = blockIdx.x, tid = threadIdx.x;
    const int lane = tid & 31, warp = tid >> 5;
    const int wq = warp & 3;      // pixel quadrant within image
    const int wb = warp >> 2;     // image within pair
    const int tig = lane & 3, g = lane >> 2;

    int bB[8];
#pragma unroll
    for (int n = 0; n < 8; ++n) {
        int p = wq * 64 + n * 8;
        bB[n] = (p >> 4) * 32 + (p & 15) + g;
    }

    float acc[4][8][4];
#pragma unroll
    for (int m = 0; m < 4; ++m)
#pragma unroll
        for (int n = 0; n < 8; ++n)
#pragma unroll
            for (int k = 0; k < 4; ++k) acc[m][n][k] = 0.f;

    int total = 0;
    for (int s = 0; s < a.nseg; ++s) total += a.seg[s].nch;
    const uint32_t smemBase = (uint32_t)__cvta_generic_to_shared(smem);

#define ISSUE(S, C8, BI) do {                                                    \
        const uint32_t dA = smemBase + (BI) * BUF_BYTES;                         \
        const uint32_t dP = dA + A_BYTES;                                        \
        const float* pw = a.PW +                                                 \
            (size_t)(cg * a.nChunks + a.seg[S].startChunk + (C8)) * 12800;       \
        for (int j = tid; j < 3200; j += CONV_THREADS)                           \
            cpasync16(dA + j * 16, pw + j * 4);                                  \
        const char* sp = (const char*)a.seg[S].pad +                             \
            (size_t)(by * 2 * a.seg[S].nch + (C8)) * PLANE_BYTES;                \
        const size_t imgStride = (size_t)a.seg[S].nch * PLANE_BYTES;             \
        for (int j = tid; j < 3840; j += CONV_THREADS) {                         \
            int img = j >> 11;  /* j/1920 via: 1920*1=1920, use compare */        \
            img = (j >= 1920) ? 1 : 0;                                           \
            int r = j - img * 1920;                                              \
            cpasync16(dP + img * PLANE_BYTES + r * 16, sp + img * imgStride + r * 16); \
        }                                                                        \
    } while (0)

    int s = 0, c8 = 0;
    ISSUE(s, c8, 0);
    cpcommit();

    for (int i = 0; i < total; ++i) {
        int sn = s, cn = c8 + 1;
        if (cn == a.seg[sn].nch) { cn = 0; ++sn; }
        if (i + 1 < total) ISSUE(sn, cn, (i + 1) & 1);
        cpcommit();
        asm volatile("cp.async.wait_group 1;");
        __syncthreads();

        const char* bufc = smem + (i & 1) * BUF_BYTES;
        const char* aB   = bufc + lane * 16;
        const char* plc  = bufc + A_BYTES + wb * PLANE_BYTES + tig * 4;

#pragma unroll
        for (int dy = 0; dy < 5; ++dy) {
#pragma unroll
            for (int dx = 0; dx < 5; ++dx) {
                const int tap = dy * 5 + dx;
                uint4 A[4];
#pragma unroll
                for (int mp = 0; mp < 4; ++mp)
                    A[mp] = *(const uint4*)(aB + tap * 2048 + mp * 512);
                const int toff = dy * 1536 + dx * 48;
#pragma unroll
                for (int n = 0; n < 8; ++n) {
                    const char* bp = plc + bB[n] * 48 + toff;
                    const uint32_t b0 = *(const uint32_t*)bp;
                    const uint32_t b1 = *(const uint32_t*)(bp + 16);
#pragma unroll
                    for (int mp = 0; mp < 4; ++mp)
                        mma_f16(acc[mp][n][0], acc[mp][n][1], acc[mp][n][2], acc[mp][n][3],
                                A[mp].x, A[mp].y, A[mp].z, A[mp].w, b0, b1);
                }
            }
        }
        __syncthreads();
        s = sn; c8 = cn;
    }
#undef ISSUE

    const int coBase = cg * 64;
    const int bimg   = by * 2 + wb;
#pragma unroll
    for (int mp = 0; mp < 4; ++mp) {
        const int row0 = coBase + mp * 16 + g;
        const int row1 = row0 + 8;
        const float bias0 = a.bias ? a.bias[row0] : 0.f;
        const float bias1 = a.bias ? a.bias[row1] : 0.f;
#pragma unroll
        for (int n = 0; n < 8; ++n) {
            const int col = wq * 64 + n * 8 + 2 * tig;
            size_t o0 = ((size_t)bimg * a.cout + row0) * PIX + col;
            size_t o1 = ((size_t)bimg * a.cout + row1) * PIX + col;
            float v0 = acc[mp][n][0] + bias0;
            float v1 = acc[mp][n][1] + bias0;
            float v2 = acc[mp][n][2] + bias1;
            float v3 = acc[mp][n][3] + bias1;
            if (a.base) {
                v0 += a.base[o0]; v1 += a.base[o0 + 1];
                v2 += a.base[o1]; v3 += a.base[o1 + 1];
            }
            a.out[o0] = v0; a.out[o0 + 1] = v1;
            a.out[o1] = v2; a.out[o1 + 1] = v3;
        }
    }
}

// ---------------- pointwise ----------------
__device__ __forceinline__ float sigmoidf_(float x) { return 1.f / (1.f + expf(-x)); }

__global__ void lstm_kernel(const float* __restrict__ gates,
                            const float* __restrict__ c_in,
                            float* __restrict__ h_exact,
                            __half* __restrict__ h_pad,
                            float* __restrict__ c_out) {
    int idx = blockIdx.x * blockDim.x + threadIdx.x;
    if (idx >= 4194304) return;
    int b = idx >> 15;
    int r = idx & 32767;
    size_t g0 = (size_t)b * 131072 + r;
    float ig = gates[g0];
    float fg = gates[g0 + 32768];
    float og = gates[g0 + 65536];
    float gg = gates[g0 + 98304];
    float c  = sigmoidf_(fg) * c_in[idx] + sigmoidf_(ig) * tanhf(gg);
    c_out[idx] = c;
    float h = sigmoidf_(og) * tanhf(c);
    if (h_exact) h_exact[idx] = h;
    int ch = r >> 8, pix = r & 255;
    int pp = ((pix >> 4) + 2) * 32 + (pix & 15) + 2;
    h_pad[((size_t)(b * 8 + (ch >> 4)) * 640 + pp) * 24 + (ch & 15)] = __float2half_rn(h);
}

__global__ void zkl_kernel(const float* __restrict__ rq,
                           const float* __restrict__ rp,
                           const float* __restrict__ eps_t,
                           float* __restrict__ z,
                           __half* __restrict__ z_pad,
                           float* __restrict__ klb,
                           float* __restrict__ lpqb) {
    const int b = blockIdx.x;
    const int tid = threadIdx.x;
    const float* rqb = rq + (size_t)b * 32768;
    const float* rpb = rp + (size_t)b * 32768;
    const float* eb  = eps_t + (size_t)b * 16384;
    float* zb = z + (size_t)b * 16384;

    float kl = 0.f, lpq = 0.f;
    for (int i = tid; i < 16384; i += 256) {
        float mq = rqb[i], lq = rqb[i + 16384];
        float mp = rpb[i], lp = rpb[i + 16384];
        float e  = eb[i];
        float zi = mq + expf(0.5f * lq) * e;
        zb[i] = zi;
        int ch = i >> 8, pix = i & 255;
        int pp = ((pix >> 4) + 2) * 32 + (pix & 15) + 2;
        z_pad[((size_t)(b * 4 + (ch >> 4)) * 640 + pp) * 24 + (ch & 15)] = __float2half_rn(zi);
        float dq = zi - mq, dp = zi - mp;
        lpq += 0.5f * ((lq + dq * dq * expf(-lq)) - (lp + dp * dp * expf(-lp)));
        float dm = mq - mp;
        kl  += 0.5f * (lp - lq + (expf(lq) + dm * dm) * expf(-lp) - 1.f);
    }
    __shared__ float s1[256], s2[256];
    s1[tid] = kl; s2[tid] = lpq;
    __syncthreads();
    for (int o = 128; o > 0; o >>= 1) {
        if (tid < o) { s1[tid] += s1[tid + o]; s2[tid] += s2[tid + o]; }
        __syncthreads();
    }
    if (tid == 0) { klb[b] += s1[0]; lpqb[b] += s2[0]; }
}

__global__ void copy_kernel(const float* __restrict__ src, float* __restrict__ dst, int n) {
    int i = blockIdx.x * blockDim.x + threadIdx.x;
    if (i < n) dst[i] = src[i];
}

__global__ void finalize_kernel(const float* __restrict__ klb,
                                const float* __restrict__ lpqb,
                                float* __restrict__ out_kl,
                                float* __restrict__ out_lpq) {
    __shared__ float s[128];
    int t = threadIdx.x;
    s[t] = klb[t];
    out_lpq[t] = lpqb[t];
    __syncthreads();
    for (int o = 64; o > 0; o >>= 1) {
        if (t < o) s[t] += s[t + o];
        __syncthreads();
    }
    if (t == 0) out_kl[0] = s[0] / 128.f;
}

// ---------------------------------------------------------------------------
static void launch_conv(const Seg* segs, int nseg, const float* PW, int nChunks,
                        const float* bias, const float* base, float* out, int cout) {
    ConvArgs a;
    for (int i = 0; i < 4; ++i) { a.seg[i].pad = nullptr; a.seg[i].nch = 0; a.seg[i].startChunk = 0; }
    for (int i = 0; i < nseg; ++i) a.seg[i] = segs[i];
    a.nseg = nseg; a.PW = PW; a.nChunks = nChunks;
    a.bias = bias; a.base = base; a.out = out; a.cout = cout;
    dim3 grid(cout / 64, BATCH / 2);
    conv5x5_mma_kernel<<<grid, CONV_THREADS, CONV_SMEM_BYTES>>>(a);
}

extern "C" void kernel_launch(void* const* d_in, const int* in_sizes, int n_in,
                              void* d_out, int out_size) {
    (void)in_sizes; (void)n_in; (void)out_size;
    const float* C_t    = (const float*)d_in[0];
    const float* D_t    = (const float*)d_in[1];
    const float* a_tmo  = (const float*)d_in[2];
    const float* s_tmo  = (const float*)d_in[3];
    const float* c_ssm_tmo = (const float*)d_in[4];
    const float* z_tmo  = (const float*)d_in[5];
    const float* eps    = (const float*)d_in[6];
    const float* W_ssm  = (const float*)d_in[7];
    const float* b_ssm  = (const float*)d_in[8];
    const float* W_p    = (const float*)d_in[9];
    const float* b_p    = (const float*)d_in[10];
    const float* W_q    = (const float*)d_in[11];
    const float* b_q    = (const float*)d_in[12];
    const float* W_rp   = (const float*)d_in[13];
    const float* b_rp   = (const float*)d_in[14];
    const float* W_rq   = (const float*)d_in[15];
    const float* b_rq   = (const float*)d_in[16];

    static int smem_set = -1;
    if (smem_set < 0) {
        cudaFuncSetAttribute(conv5x5_mma_kernel,
                             cudaFuncAttributeMaxDynamicSharedMemorySize, CONV_SMEM_BYTES);
        smem_set = 1;
    }

    float* S;
    cudaGetSymbolAddress((void**)&S, g_scratch);
    float* static_q = S + OFF_STATIC_Q;
    float* static_p = S + OFF_STATIC_P;
    float* gates    = S + OFF_GATES;
    float* cp = S + OFF_CP;
    float* cq = S + OFF_CQ;
    float* rq = S + OFF_RQ;
    float* rp = S + OFF_RP;
    float* zb = S + OFF_Z;
    float* klb  = S + OFF_KLB;
    float* lpqb = S + OFF_LPQB;
    float* pw_ssm = S + OFF_PW_SSM;
    float* pw_q   = S + OFF_PW_Q;
    float* pw_p   = S + OFF_PW_P;
    float* pw_rq  = S + OFF_PW_RQ;
    float* pw_rp  = S + OFF_PW_RP;
    __half* pad_C    = (__half*)(S + OFF_PAD_C);
    __half* pad_D    = (__half*)(S + OFF_PAD_D);
    __half* pad_a    = (__half*)(S + OFF_PAD_A);
    __half* pad_stmo = (__half*)(S + OFF_PAD_STMO);
    __half* pad_ztmo = (__half*)(S + OFF_PAD_ZTMO);
    __half* pad_st   = (__half*)(S + OFF_PAD_ST);
    __half* pad_hp   = (__half*)(S + OFF_PAD_HP);
    __half* pad_hq   = (__half*)(S + OFF_PAD_HQ);
    __half* pad_zb   = (__half*)(S + OFF_PAD_ZB);

    float* out    = (float*)d_out;
    float* out_z  = out;
    float* out_s  = out + 2097152;
    float* out_c  = out + 6291456;
    float* out_kl = out + 10485760;
    float* out_lpq= out + 10485761;

    // per-call zeroing: states + accumulators + padded state planes
    cudaMemsetAsync(cp,  0, (size_t)2 * 4194304 * sizeof(float));
    cudaMemsetAsync(klb, 0, 256 * sizeof(float));
    cudaMemsetAsync(pad_st, 0, (size_t)PAD_STATE_FLOATS * sizeof(float));

    // ---- combined repack ----
    {
        RepackJobs J;
        J.W[0]=W_ssm; J.PW[0]=pw_ssm; J.cinSrc[0]=328; J.nch[0]=21; J.nSeg[0]=4;
        int sp0[4]={0,64,192,208}, sl0[4]={64,128,8,128}, ss0[4]={0,64,192,200};
        J.W[1]=W_q; J.PW[1]=pw_q; J.cinSrc[1]=520; J.nch[1]=33; J.nSeg[1]=5;
        int sp1[5]={0,128,256,384,400}, sl1[5]={128,128,128,8,128}, ss1[5]={0,128,256,384,392};
        J.W[2]=W_p; J.PW[2]=pw_p; J.cinSrc[2]=456; J.nch[2]=29; J.nSeg[2]=5;
        int sp2[5]={0,64,192,320,336}, sl2[5]={64,128,128,8,128}, ss2[5]={0,64,192,320,328};
        J.W[3]=W_rq; J.PW[3]=pw_rq; J.cinSrc[3]=128; J.nch[3]=8; J.nSeg[3]=1;
        J.W[4]=W_rp; J.PW[4]=pw_rp; J.cinSrc[4]=128; J.nch[4]=8; J.nSeg[4]=1;
        for (int k = 0; k < 4; ++k) { J.segPad[0][k]=sp0[k]; J.segLen[0][k]=sl0[k]; J.segSrc[0][k]=ss0[k]; }
        for (int k = 0; k < 5; ++k) { J.segPad[1][k]=sp1[k]; J.segLen[1][k]=sl1[k]; J.segSrc[1][k]=ss1[k]; }
        for (int k = 0; k < 5; ++k) { J.segPad[2][k]=sp2[k]; J.segLen[2][k]=sl2[k]; J.segSrc[2][k]=ss2[k]; }
        J.segPad[3][0]=0; J.segLen[3][0]=128; J.segSrc[3][0]=0;
        J.segPad[4][0]=0; J.segLen[4][0]=128; J.segSrc[4][0]=0;
        int cgs[5] = {8, 8, 8, 2, 2};
        J.start[0] = 0;
        for (int i = 0; i < 5; ++i) J.start[i + 1] = J.start[i] + cgs[i] * J.nch[i] * 12800;
        repack_all_kernel<<<(J.start[5] + 255) / 256, 256>>>(J);
    }

    // ---- combined padify ----
    {
        PadJobs J;
        J.src[0]=C_t;   J.dst[0]=pad_C;    J.cinReal[0]=128; J.nch[0]=8;
        J.src[1]=D_t;   J.dst[1]=pad_D;    J.cinReal[1]=128; J.nch[1]=8;
        J.src[2]=a_tmo; J.dst[2]=pad_a;    J.cinReal[2]=8;   J.nch[2]=1;
        J.src[3]=s_tmo; J.dst[3]=pad_stmo; J.cinReal[3]=128; J.nch[3]=8;
        J.src[4]=z_tmo; J.dst[4]=pad_ztmo; J.cinReal[4]=64;  J.nch[4]=4;
        J.start[0] = 0;
        for (int i = 0; i < 5; ++i) J.start[i + 1] = J.start[i] + BATCH * J.nch[i] * 640 * 8;
        padify_all_kernel<<<(J.start[5] + 255) / 256, 256>>>(J);
    }

    // ---- SSM conv: chunks z 0-3, C 4-11, a 12, s 13-20 (nChunks 21) ----
    {
        Seg segs[4] = { {pad_ztmo,4,0}, {pad_C,8,4}, {pad_a,1,12}, {pad_stmo,8,13} };
        launch_conv(segs, 4, pw_ssm, 21, b_ssm, nullptr, gates, 512);
        lstm_kernel<<<16384, 256>>>(gates, c_ssm_tmo, out_s, pad_st, out_c);
    }
    // ---- static q: D 8-15, s_t 16-23, a 24  (q chunks: hp 0-7, hq 25-32; nChunks 33) ----
    {
        Seg segs[3] = { {pad_D,8,8}, {pad_st,8,16}, {pad_a,1,24} };
        launch_conv(segs, 3, pw_q, 33, b_q, nullptr, static_q, 512);
    }
    // ---- static p: C 4-11, s_t 12-19, a 20 (p chunks: z 0-3, hp 21-28; nChunks 29) ----
    {
        Seg segs[3] = { {pad_C,8,4}, {pad_st,8,12}, {pad_a,1,20} };
        launch_conv(segs, 3, pw_p, 29, b_p, nullptr, static_p, 512);
    }

    for (int t = 0; t < STEPS; ++t) {
        {
            Seg segs[2] = { {pad_hp,8,0}, {pad_hq,8,25} };
            launch_conv(segs, 2, pw_q, 33, nullptr, static_q, gates, 512);
        }
        lstm_kernel<<<16384, 256>>>(gates, cq, nullptr, pad_hq, cq);

        {
            Seg segs[1] = { {pad_hq,8,0} };
            launch_conv(segs, 1, pw_rq, 8, b_rq, nullptr, rq, 128);
        }
        {
            Seg segs[1] = { {pad_hp,8,0} };
            launch_conv(segs, 1, pw_rp, 8, b_rp, nullptr, rp, 128);
        }

        zkl_kernel<<<128, 256>>>(rq, rp, eps + (size_t)t * 2097152, zb, pad_zb, klb, lpqb);

        {
            Seg segs[2] = { {pad_zb,4,0}, {pad_hp,8,21} };
            launch_conv(segs, 2, pw_p, 29, nullptr, static_p, gates, 512);
        }
        lstm_kernel<<<16384, 256>>>(gates, cp, nullptr, pad_hp, cp);
    }

    copy_kernel<<<(2097152 + 255) / 256, 256>>>(zb, out_z, 2097152);
    finalize_kernel<<<1, 128>>>(klb, lpqb, out_kl, out_lpq);
}

// round 15
// speedup vs baseline: 1.1199x; 1.1199x over previous
#include <cuda_runtime.h>
#include <cuda_fp16.h>
#include <cstdint>
#include <math.h>

// fp16 m16n8k16 mma conv (fp32 accum), cp.async double-buffered pipeline.
// R15: R14 fused-LSTM epilogue + ping-pong hp/hq pads (fixes RAW race).
#define PIX   256
#define BATCH 128
#define STEPS 6

// scratch offsets (floats)
#define OFF_STATIC_Q 0u
#define OFF_STATIC_P 16777216u
#define OFF_CP       50331648u
#define OFF_CQ       54525952u
#define OFF_RQ       58720256u
#define OFF_RP       62914560u
#define OFF_KLB      69206016u
#define OFF_LPQB     69206144u
#define OFF_PW_SSM   69206272u
#define OFF_PW_Q     71356672u
#define OFF_PW_P     74735872u
#define OFF_PW_RQ    77705472u
#define OFF_PW_RP    77910272u
#define OFF_PAD_C    78115072u
#define OFF_PAD_D    85979392u
#define OFF_PAD_A    93843712u
#define OFF_PAD_STMO 94826752u
#define OFF_PAD_ZTMO 102691072u
#define OFF_PAD_ST   106623232u
#define OFF_PAD_HP0  114487552u
#define OFF_PAD_HP1  122351872u
#define OFF_PAD_HQ0  130216192u
#define OFF_PAD_HQ1  138080512u
#define OFF_PAD_ZB   145944832u
#define SCRATCH_N    149876992u
// pad_st + hp0 + hp1 + hq0 + hq1 + zb (floats)
#define PAD_STATE_FLOATS 43253760u

__device__ float g_scratch[SCRATCH_N];

__device__ __forceinline__ void mma_f16(float& c0, float& c1, float& c2, float& c3,
                                        uint32_t a0, uint32_t a1, uint32_t a2, uint32_t a3,
                                        uint32_t b0, uint32_t b1) {
    asm volatile(
        "mma.sync.aligned.m16n8k16.row.col.f32.f16.f16.f32 "
        "{%0,%1,%2,%3}, {%4,%5,%6,%7}, {%8,%9}, {%0,%1,%2,%3};"
        : "+f"(c0), "+f"(c1), "+f"(c2), "+f"(c3)
        : "r"(a0), "r"(a1), "r"(a2), "r"(a3), "r"(b0), "r"(b1));
}
__device__ __forceinline__ void cpasync16(uint32_t s, const void* g) {
    asm volatile("cp.async.cg.shared.global [%0], [%1], 16;" :: "r"(s), "l"(g));
}
__device__ __forceinline__ void cpcommit() { asm volatile("cp.async.commit_group;"); }
__device__ __forceinline__ uint32_t pack_h2(float lo, float hi) {
    __half2 h = __floats2half2_rn(lo, hi);
    return *reinterpret_cast<uint32_t*>(&h);
}
__device__ __forceinline__ float sigmoidf_(float x) { return 1.f / (1.f + expf(-x)); }

// ---------------- weight repack (fp16 fragments) ----------------
// PW per (cg64, chunk16): [tap25][mp4][lane32][slot4] uint32 = 12800 u32.
// gIL=1: co_src = mp*128 + cg*16 + ... (gate-interleaved for fused LSTM).
struct RepackJobs {
    const float* W[5]; float* PW[5];
    int cinSrc[5], nch[5], nSeg[5], gIL[5];
    int segPad[5][5], segLen[5][5], segSrc[5][5];
    int start[6];
};
__device__ __forceinline__ float w_lookup(const RepackJobs& J, int j, int co, int ci, int tap) {
    int s = J.nSeg[j] - 1;
    for (int t = 1; t < J.nSeg[j]; ++t) if (ci < J.segPad[j][t]) { s = t - 1; break; }
    int off = ci - J.segPad[j][s];
    if (off >= J.segLen[j][s]) return 0.f;
    return J.W[j][((size_t)co * J.cinSrc[j] + J.segSrc[j][s] + off) * 25 + tap];
}
__global__ void repack_all_kernel(RepackJobs J) {
    int idx = blockIdx.x * 256 + threadIdx.x;
    if (idx >= J.start[5]) return;
    int j = 0; while (idx >= J.start[j + 1]) ++j;
    int L = idx - J.start[j];
    int s = L & 3, lane = (L >> 2) & 31, mp = (L >> 7) & 3;
    int rest = L >> 9;
    int tap = rest % 25, rest2 = rest / 25;
    int chunk = rest2 % J.nch[j], cg = rest2 / J.nch[j];
    int g = lane >> 2, tig = lane & 3;
    int sub = (s & 1) * 8 + g;
    int co  = J.gIL[j] ? (mp * 128 + cg * 16 + sub) : (cg * 64 + mp * 16 + sub);
    int ci0 = chunk * 16 + 2 * tig + (s >> 1) * 8;
    reinterpret_cast<uint32_t*>(J.PW[j])[L] =
        pack_h2(w_lookup(J, j, co, ci0, tap), w_lookup(J, j, co, ci0 + 1, tap));
}

// ---------------- padify (fp16 planes) ----------------
struct PadJobs {
    const float* src[5]; __half* dst[5];
    int cinReal[5], nch[5];
    int start[6];
};
__global__ void padify_all_kernel(PadJobs J) {
    int idx = blockIdx.x * 256 + threadIdx.x;
    if (idx >= J.start[5]) return;
    int j = 0; while (idx >= J.start[j + 1]) ++j;
    int L = idx - J.start[j];
    int u = L & 7;
    int pix = (L >> 3) % 640;
    int rest = L / (640 * 8);
    int ch = rest % J.nch[j], b = rest / J.nch[j];
    int row = pix >> 5, col = pix & 31;
    float v0 = 0.f, v1 = 0.f;
    if ((unsigned)(row - 2) < 16u && (unsigned)(col - 2) < 16u) {
        int ci0 = ch * 16 + 2 * u;
        int p = (row - 2) * 16 + (col - 2);
        if (ci0 < J.cinReal[j])     v0 = J.src[j][((size_t)b * J.cinReal[j] + ci0) * 256 + p];
        if (ci0 + 1 < J.cinReal[j]) v1 = J.src[j][((size_t)b * J.cinReal[j] + ci0 + 1) * 256 + p];
    }
    reinterpret_cast<uint32_t*>(J.dst[j])[((size_t)(b * J.nch[j] + ch) * 640 + pix) * 12 + u] =
        pack_h2(v0, v1);
}

// ---------------- conv ----------------
struct Seg { const __half* pad; int nch; int startChunk; };
struct ConvArgs {
    Seg seg[4]; int nseg;
    const float* PW; int nChunks;
    const float* bias; const float* base;
    float* out; int cout;
    int gateIL;
    int fuse;
    const float* cin;
    float* hex;
    __half* hpad;
    float* cptr;
};
#define A_BYTES     51200
#define PLANE_BYTES 30720
#define BUF_BYTES   (A_BYTES + PLANE_BYTES)
#define CONV_SMEM_BYTES (2 * BUF_BYTES)   // 163840
#define CONV_THREADS 256

__global__ void __launch_bounds__(CONV_THREADS, 1) conv5x5_mma_kernel(ConvArgs a) {
    extern __shared__ char smem[];
    const int b = blockIdx.y, cg = blockIdx.x, tid = threadIdx.x;
    const int lane = tid & 31, warp = tid >> 5;
    const int tig = lane & 3, g = lane >> 2;

    int bB[4];
#pragma unroll
    for (int n = 0; n < 4; ++n) {
        int p = warp * 32 + n * 8;
        bB[n] = (p >> 4) * 32 + (p & 15) + g;
    }

    float acc[4][4][4];
#pragma unroll
    for (int m = 0; m < 4; ++m)
#pragma unroll
        for (int n = 0; n < 4; ++n)
#pragma unroll
            for (int k = 0; k < 4; ++k) acc[m][n][k] = 0.f;

    int total = 0;
    for (int s = 0; s < a.nseg; ++s) total += a.seg[s].nch;
    const uint32_t smemBase = (uint32_t)__cvta_generic_to_shared(smem);

#define ISSUE(S, C8, BI) do {                                                    \
        const uint32_t dA = smemBase + (BI) * BUF_BYTES;                         \
        const uint32_t dP = dA + A_BYTES;                                        \
        const float* pw = a.PW +                                                 \
            (size_t)(cg * a.nChunks + a.seg[S].startChunk + (C8)) * 12800;       \
        for (int j = tid; j < 3200; j += CONV_THREADS)                           \
            cpasync16(dA + j * 16, pw + j * 4);                                  \
        const char* sp = (const char*)a.seg[S].pad +                             \
            (size_t)(b * a.seg[S].nch + (C8)) * PLANE_BYTES;                     \
        for (int j = tid; j < 1920; j += CONV_THREADS)                           \
            cpasync16(dP + j * 16, sp + j * 16);                                 \
    } while (0)

    int s = 0, c8 = 0;
    ISSUE(s, c8, 0);
    cpcommit();

    for (int i = 0; i < total; ++i) {
        int sn = s, cn = c8 + 1;
        if (cn == a.seg[sn].nch) { cn = 0; ++sn; }
        if (i + 1 < total) ISSUE(sn, cn, (i + 1) & 1);
        cpcommit();
        asm volatile("cp.async.wait_group 1;");
        __syncthreads();

        const char* bufc = smem + (i & 1) * BUF_BYTES;
        const char* aB   = bufc + lane * 16;
        const char* plc  = bufc + A_BYTES + tig * 4;

#pragma unroll
        for (int dy = 0; dy < 5; ++dy) {
#pragma unroll
            for (int dx = 0; dx < 5; ++dx) {
                const int tap = dy * 5 + dx;
                uint4 A[4];
#pragma unroll
                for (int mp = 0; mp < 4; ++mp)
                    A[mp] = *(const uint4*)(aB + tap * 2048 + mp * 512);
                const int toff = dy * 1536 + dx * 48;
#pragma unroll
                for (int n = 0; n < 4; ++n) {
                    const char* bp = plc + bB[n] * 48 + toff;
                    const uint32_t b0 = *(const uint32_t*)bp;
                    const uint32_t b1 = *(const uint32_t*)(bp + 16);
#pragma unroll
                    for (int mp = 0; mp < 4; ++mp)
                        mma_f16(acc[mp][n][0], acc[mp][n][1], acc[mp][n][2], acc[mp][n][3],
                                A[mp].x, A[mp].y, A[mp].z, A[mp].w, b0, b1);
                }
            }
        }
        __syncthreads();
        s = sn; c8 = cn;
    }
#undef ISSUE

    if (!a.fuse) {
        const int coBase = cg * 64;
#pragma unroll
        for (int mp = 0; mp < 4; ++mp) {
            const int row0 = coBase + mp * 16 + g;
            const int row1 = row0 + 8;
            const int bs0  = a.gateIL ? (mp * 128 + cg * 16 + g) : row0;
            const float bias0 = a.bias ? a.bias[bs0] : 0.f;
            const float bias1 = a.bias ? a.bias[bs0 + 8] : 0.f;
#pragma unroll
            for (int n = 0; n < 4; ++n) {
                const int col = warp * 32 + n * 8 + 2 * tig;
                size_t o0 = ((size_t)b * a.cout + row0) * PIX + col;
                size_t o1 = ((size_t)b * a.cout + row1) * PIX + col;
                float v0 = acc[mp][n][0] + bias0;
                float v1 = acc[mp][n][1] + bias0;
                float v2 = acc[mp][n][2] + bias1;
                float v3 = acc[mp][n][3] + bias1;
                if (a.base) {
                    v0 += a.base[o0]; v1 += a.base[o0 + 1];
                    v2 += a.base[o1]; v3 += a.base[o1 + 1];
                }
                a.out[o0] = v0; a.out[o0 + 1] = v1;
                a.out[o1] = v2; a.out[o1 + 1] = v3;
            }
        }
    } else {
        // fused LSTM epilogue: mp = gate (i,f,o,g) of lstm channels cg*16 + {g, 8+g}
        float bi[4][2];
#pragma unroll
        for (int gate = 0; gate < 4; ++gate)
#pragma unroll
            for (int half = 0; half < 2; ++half)
                bi[gate][half] = a.bias ? a.bias[gate * 128 + cg * 16 + half * 8 + g] : 0.f;
#pragma unroll
        for (int n = 0; n < 4; ++n) {
            const int col = warp * 32 + n * 8 + 2 * tig;
#pragma unroll
            for (int half = 0; half < 2; ++half) {
                const int ch = cg * 16 + half * 8 + g;
#pragma unroll
                for (int e = 0; e < 2; ++e) {
                    const int k = half * 2 + e;
                    const int pix = col + e;
                    float ig = acc[0][n][k] + bi[0][half];
                    float fg = acc[1][n][k] + bi[1][half];
                    float og = acc[2][n][k] + bi[2][half];
                    float gg = acc[3][n][k] + bi[3][half];
                    if (a.base) {
                        size_t ob = ((size_t)(b * 512 + cg * 64 + half * 8 + g)) * 256 + pix;
                        ig += a.base[ob];
                        fg += a.base[ob + 4096];
                        og += a.base[ob + 8192];
                        gg += a.base[ob + 12288];
                    }
                    size_t ci = ((size_t)(b * 128 + ch)) * 256 + pix;
                    float cold = a.cin[ci];
                    float c2 = sigmoidf_(fg) * cold + sigmoidf_(ig) * tanhf(gg);
                    a.cptr[ci] = c2;
                    float h = sigmoidf_(og) * tanhf(c2);
                    if (a.hex) a.hex[ci] = h;
                    int pp = ((pix >> 4) + 2) * 32 + (pix & 15) + 2;
                    a.hpad[((size_t)(b * 8 + (ch >> 4)) * 640 + pp) * 24 + (ch & 15)] =
                        __float2half_rn(h);
                }
            }
        }
    }
}

// ---------------- zkl ----------------
__global__ void zkl_kernel(const float* __restrict__ rq,
                           const float* __restrict__ rp,
                           const float* __restrict__ eps_t,
                           float* __restrict__ z,
                           __half* __restrict__ z_pad,
                           float* __restrict__ klb,
                           float* __restrict__ lpqb) {
    const int b = blockIdx.x;
    const int tid = threadIdx.x;
    const float* rqb = rq + (size_t)b * 32768;
    const float* rpb = rp + (size_t)b * 32768;
    const float* eb  = eps_t + (size_t)b * 16384;

    float kl = 0.f, lpq = 0.f;
    for (int i = tid; i < 16384; i += 256) {
        float mq = rqb[i], lq = rqb[i + 16384];
        float mp = rpb[i], lp = rpb[i + 16384];
        float e  = eb[i];
        float zi = mq + expf(0.5f * lq) * e;
        if (z) z[(size_t)b * 16384 + i] = zi;
        int ch = i >> 8, pix = i & 255;
        int pp = ((pix >> 4) + 2) * 32 + (pix & 15) + 2;
        z_pad[((size_t)(b * 4 + (ch >> 4)) * 640 + pp) * 24 + (ch & 15)] = __float2half_rn(zi);
        float dq = zi - mq, dp = zi - mp;
        lpq += 0.5f * ((lq + dq * dq * expf(-lq)) - (lp + dp * dp * expf(-lp)));
        float dm = mq - mp;
        kl  += 0.5f * (lp - lq + (expf(lq) + dm * dm) * expf(-lp) - 1.f);
    }
    __shared__ float s1[256], s2[256];
    s1[tid] = kl; s2[tid] = lpq;
    __syncthreads();
    for (int o = 128; o > 0; o >>= 1) {
        if (tid < o) { s1[tid] += s1[tid + o]; s2[tid] += s2[tid + o]; }
        __syncthreads();
    }
    if (tid == 0) { klb[b] += s1[0]; lpqb[b] += s2[0]; }
}

__global__ void finalize_kernel(const float* __restrict__ klb,
                                const float* __restrict__ lpqb,
                                float* __restrict__ out_kl,
                                float* __restrict__ out_lpq) {
    __shared__ float s[128];
    int t = threadIdx.x;
    s[t] = klb[t];
    out_lpq[t] = lpqb[t];
    __syncthreads();
    for (int o = 64; o > 0; o >>= 1) {
        if (t < o) s[t] += s[t + o];
        __syncthreads();
    }
    if (t == 0) out_kl[0] = s[0] / 128.f;
}

// ---------------------------------------------------------------------------
static void conv_common(ConvArgs& a, const Seg* segs, int nseg, const float* PW,
                        int nChunks) {
    for (int i = 0; i < 4; ++i) { a.seg[i].pad = nullptr; a.seg[i].nch = 0; a.seg[i].startChunk = 0; }
    for (int i = 0; i < nseg; ++i) a.seg[i] = segs[i];
    a.nseg = nseg; a.PW = PW; a.nChunks = nChunks;
    a.bias = nullptr; a.base = nullptr; a.out = nullptr; a.cout = 512;
    a.gateIL = 0; a.fuse = 0;
    a.cin = nullptr; a.hex = nullptr; a.hpad = nullptr; a.cptr = nullptr;
}

static void launch_conv_plain(const Seg* segs, int nseg, const float* PW, int nChunks,
                              const float* bias, const float* base, float* out,
                              int cout, int gateIL) {
    ConvArgs a;
    conv_common(a, segs, nseg, PW, nChunks);
    a.bias = bias; a.base = base; a.out = out; a.cout = cout; a.gateIL = gateIL;
    dim3 grid(cout / 64, BATCH);
    conv5x5_mma_kernel<<<grid, CONV_THREADS, CONV_SMEM_BYTES>>>(a);
}

static void launch_conv_lstm(const Seg* segs, int nseg, const float* PW, int nChunks,
                             const float* bias, const float* base,
                             const float* cin, float* hex, __half* hpad, float* cptr) {
    ConvArgs a;
    conv_common(a, segs, nseg, PW, nChunks);
    a.bias = bias; a.base = base; a.fuse = 1; a.gateIL = 1;
    a.cin = cin; a.hex = hex; a.hpad = hpad; a.cptr = cptr;
    dim3 grid(8, BATCH);
    conv5x5_mma_kernel<<<grid, CONV_THREADS, CONV_SMEM_BYTES>>>(a);
}

extern "C" void kernel_launch(void* const* d_in, const int* in_sizes, int n_in,
                              void* d_out, int out_size) {
    (void)in_sizes; (void)n_in; (void)out_size;
    const float* C_t    = (const float*)d_in[0];
    const float* D_t    = (const float*)d_in[1];
    const float* a_tmo  = (const float*)d_in[2];
    const float* s_tmo  = (const float*)d_in[3];
    const float* c_ssm_tmo = (const float*)d_in[4];
    const float* z_tmo  = (const float*)d_in[5];
    const float* eps    = (const float*)d_in[6];
    const float* W_ssm  = (const float*)d_in[7];
    const float* b_ssm  = (const float*)d_in[8];
    const float* W_p    = (const float*)d_in[9];
    const float* b_p    = (const float*)d_in[10];
    const float* W_q    = (const float*)d_in[11];
    const float* b_q    = (const float*)d_in[12];
    const float* W_rp   = (const float*)d_in[13];
    const float* b_rp   = (const float*)d_in[14];
    const float* W_rq   = (const float*)d_in[15];
    const float* b_rq   = (const float*)d_in[16];

    static int smem_set = -1;
    if (smem_set < 0) {
        cudaFuncSetAttribute(conv5x5_mma_kernel,
                             cudaFuncAttributeMaxDynamicSharedMemorySize, CONV_SMEM_BYTES);
        smem_set = 1;
    }

    float* S;
    cudaGetSymbolAddress((void**)&S, g_scratch);
    float* static_q = S + OFF_STATIC_Q;
    float* static_p = S + OFF_STATIC_P;
    float* cp = S + OFF_CP;
    float* cq = S + OFF_CQ;
    float* rq = S + OFF_RQ;
    float* rp = S + OFF_RP;
    float* klb  = S + OFF_KLB;
    float* lpqb = S + OFF_LPQB;
    float* pw_ssm = S + OFF_PW_SSM;
    float* pw_q   = S + OFF_PW_Q;
    float* pw_p   = S + OFF_PW_P;
    float* pw_rq  = S + OFF_PW_RQ;
    float* pw_rp  = S + OFF_PW_RP;
    __half* pad_C    = (__half*)(S + OFF_PAD_C);
    __half* pad_D    = (__half*)(S + OFF_PAD_D);
    __half* pad_a    = (__half*)(S + OFF_PAD_A);
    __half* pad_stmo = (__half*)(S + OFF_PAD_STMO);
    __half* pad_ztmo = (__half*)(S + OFF_PAD_ZTMO);
    __half* pad_st   = (__half*)(S + OFF_PAD_ST);
    __half* pad_hp[2] = { (__half*)(S + OFF_PAD_HP0), (__half*)(S + OFF_PAD_HP1) };
    __half* pad_hq[2] = { (__half*)(S + OFF_PAD_HQ0), (__half*)(S + OFF_PAD_HQ1) };
    __half* pad_zb   = (__half*)(S + OFF_PAD_ZB);

    float* out    = (float*)d_out;
    float* out_z  = out;
    float* out_s  = out + 2097152;
    float* out_c  = out + 6291456;
    float* out_kl = out + 10485760;
    float* out_lpq= out + 10485761;

    // per-call zeroing: states + accumulators + ALL padded state planes (both parities)
    cudaMemsetAsync(cp,  0, (size_t)2 * 4194304 * sizeof(float));
    cudaMemsetAsync(klb, 0, 256 * sizeof(float));
    cudaMemsetAsync(pad_st, 0, (size_t)PAD_STATE_FLOATS * sizeof(float));

    // ---- combined repack ----
    {
        RepackJobs J;
        J.W[0]=W_ssm; J.PW[0]=pw_ssm; J.cinSrc[0]=328; J.nch[0]=21; J.nSeg[0]=4; J.gIL[0]=1;
        int sp0[4]={0,64,192,208}, sl0[4]={64,128,8,128}, ss0[4]={0,64,192,200};
        J.W[1]=W_q; J.PW[1]=pw_q; J.cinSrc[1]=520; J.nch[1]=33; J.nSeg[1]=5; J.gIL[1]=1;
        int sp1[5]={0,128,256,384,400}, sl1[5]={128,128,128,8,128}, ss1[5]={0,128,256,384,392};
        J.W[2]=W_p; J.PW[2]=pw_p; J.cinSrc[2]=456; J.nch[2]=29; J.nSeg[2]=5; J.gIL[2]=1;
        int sp2[5]={0,64,192,320,336}, sl2[5]={64,128,128,8,128}, ss2[5]={0,64,192,320,328};
        J.W[3]=W_rq; J.PW[3]=pw_rq; J.cinSrc[3]=128; J.nch[3]=8; J.nSeg[3]=1; J.gIL[3]=0;
        J.W[4]=W_rp; J.PW[4]=pw_rp; J.cinSrc[4]=128; J.nch[4]=8; J.nSeg[4]=1; J.gIL[4]=0;
        for (int k = 0; k < 4; ++k) { J.segPad[0][k]=sp0[k]; J.segLen[0][k]=sl0[k]; J.segSrc[0][k]=ss0[k]; }
        for (int k = 0; k < 5; ++k) { J.segPad[1][k]=sp1[k]; J.segLen[1][k]=sl1[k]; J.segSrc[1][k]=ss1[k]; }
        for (int k = 0; k < 5; ++k) { J.segPad[2][k]=sp2[k]; J.segLen[2][k]=sl2[k]; J.segSrc[2][k]=ss2[k]; }
        J.segPad[3][0]=0; J.segLen[3][0]=128; J.segSrc[3][0]=0;
        J.segPad[4][0]=0; J.segLen[4][0]=128; J.segSrc[4][0]=0;
        int cgs[5] = {8, 8, 8, 2, 2};
        J.start[0] = 0;
        for (int i = 0; i < 5; ++i) J.start[i + 1] = J.start[i] + cgs[i] * J.nch[i] * 12800;
        repack_all_kernel<<<(J.start[5] + 255) / 256, 256>>>(J);
    }

    // ---- combined padify ----
    {
        PadJobs J;
        J.src[0]=C_t;   J.dst[0]=pad_C;    J.cinReal[0]=128; J.nch[0]=8;
        J.src[1]=D_t;   J.dst[1]=pad_D;    J.cinReal[1]=128; J.nch[1]=8;
        J.src[2]=a_tmo; J.dst[2]=pad_a;    J.cinReal[2]=8;   J.nch[2]=1;
        J.src[3]=s_tmo; J.dst[3]=pad_stmo; J.cinReal[3]=128; J.nch[3]=8;
        J.src[4]=z_tmo; J.dst[4]=pad_ztmo; J.cinReal[4]=64;  J.nch[4]=4;
        J.start[0] = 0;
        for (int i = 0; i < 5; ++i) J.start[i + 1] = J.start[i] + BATCH * J.nch[i] * 640 * 8;
        padify_all_kernel<<<(J.start[5] + 255) / 256, 256>>>(J);
    }

    // ---- SSM conv + fused LSTM (no race: reads stmo, writes st) ----
    {
        Seg segs[4] = { {pad_ztmo,4,0}, {pad_C,8,4}, {pad_a,1,12}, {pad_stmo,8,13} };
        launch_conv_lstm(segs, 4, pw_ssm, 21, b_ssm, nullptr,
                         c_ssm_tmo, out_s, pad_st, out_c);
    }
    // ---- static q: D 8-15, s_t 16-23, a 24 ----
    {
        Seg segs[3] = { {pad_D,8,8}, {pad_st,8,16}, {pad_a,1,24} };
        launch_conv_plain(segs, 3, pw_q, 33, b_q, nullptr, static_q, 512, 1);
    }
    // ---- static p: C 4-11, s_t 12-19, a 20 ----
    {
        Seg segs[3] = { {pad_C,8,4}, {pad_st,8,12}, {pad_a,1,20} };
        launch_conv_plain(segs, 3, pw_p, 29, b_p, nullptr, static_p, 512, 1);
    }

    for (int t = 0; t < STEPS; ++t) {
        const int pr = t & 1;        // read parity
        const int pw = pr ^ 1;       // write parity
        // q conv + fused q-LSTM: reads hp[pr], hq[pr]; writes hq[pw]
        {
            Seg segs[2] = { {pad_hp[pr],8,0}, {pad_hq[pr],8,25} };
            launch_conv_lstm(segs, 2, pw_q, 33, nullptr, static_q,
                             cq, nullptr, pad_hq[pw], cq);
        }
        // rq(new hq), rp(current hp)
        {
            Seg segs[1] = { {pad_hq[pw],8,0} };
            launch_conv_plain(segs, 1, pw_rq, 8, b_rq, nullptr, rq, 128, 0);
        }
        {
            Seg segs[1] = { {pad_hp[pr],8,0} };
            launch_conv_plain(segs, 1, pw_rp, 8, b_rp, nullptr, rp, 128, 0);
        }

        zkl_kernel<<<128, 256>>>(rq, rp, eps + (size_t)t * 2097152,
                                 (t == STEPS - 1) ? out_z : nullptr,
                                 pad_zb, klb, lpqb);

        // p conv + fused p-LSTM: reads z, hp[pr]; writes hp[pw]
        {
            Seg segs[2] = { {pad_zb,4,0}, {pad_hp[pr],8,21} };
            launch_conv_lstm(segs, 2, pw_p, 29, nullptr, static_p,
                             cp, nullptr, pad_hp[pw], cp);
        }
    }

    finalize_kernel<<<1, 128>>>(klb, lpqb, out_kl, out_lpq);
}